// round 4
// baseline (speedup 1.0000x reference)
#include <cuda_runtime.h>
#include <cstddef>
#include <cstdint>

// ---------------- problem constants ----------------
#define TT   336
#define NN   3233
#define EE   20000
#define FEAT 14
#define DD   64
#define HH   128
#define G4   512           // 4*H gate width
#define KTOT 192           // D + H contraction length (x part + h part)
#define MNODES 22
#define NBLK 147           // ceil(3233/22)
#define TC1  16            // timesteps per block, fused agg1+W2 kernel
#define TC2  4             // timesteps per block, agg2 kernel

// ---------------- device scratch (static; no allocations) ----------------
__device__ float g_deg[NN];
__device__ float g_dinv[NN];
__device__ int   g_cnt[NN];
__device__ int   g_fill[NN];
__device__ int   g_rowptr[NN + 1];
__device__ int   g_srcs[EE];
__device__ float g_norms[EE];

__device__ float g_hw1[(size_t)TT * NN * DD];   // x @ W1
__device__ float g_hw2[(size_t)TT * NN * DD];   // relu(agg1+b1) @ W2
__device__ float g_emb[(size_t)TT * NN * DD];   // agg2 + b2 + county_bias

__device__ float4 g_WT4[KTOT / 4 * G4];         // [kk][j][4] combined W_ih|W_hh, k-transposed
__device__ float  g_bsum[G4];                   // b_ih + b_hh
__device__ float  g_hfinal[NN * HH];

// ---------------- fast, accurate activations ----------------
__device__ __forceinline__ float sigf(float x) {
    return __fdividef(1.0f, 1.0f + __expf(-x));      // MUFU.EX2 + MUFU.RCP, err ~1e-6
}
__device__ __forceinline__ float tanhf_fast(float x) {
    return 2.0f * sigf(2.0f * x) - 1.0f;
}

// ---------------- packed fp32x2 FMA (FFMA2; PTX-only, 2x fp32 roofline) ----------------
__device__ __forceinline__ void ffma2(unsigned long long& acc,
                                      unsigned long long a,
                                      unsigned long long w) {
    asm("fma.rn.f32x2 %0, %1, %2, %0;" : "+l"(acc) : "l"(a), "l"(w));
}
__device__ __forceinline__ float pairsum(unsigned long long p) {
    return __uint_as_float((unsigned)p) + __uint_as_float((unsigned)(p >> 32));
}

// ---------------- graph prep ----------------
__global__ void k_init() {
    int n = blockIdx.x * blockDim.x + threadIdx.x;
    if (n < NN) { g_deg[n] = 1.0f; g_cnt[n] = 0; g_fill[n] = 0; }  // self-loop weight 1
}

__global__ void k_deg(const int* __restrict__ ei, const float* __restrict__ ew) {
    int e = blockIdx.x * blockDim.x + threadIdx.x;
    if (e < EE) {
        int dn = ei[EE + e];
        atomicAdd(&g_deg[dn], ew[e]);
        atomicAdd(&g_cnt[dn], 1);
    }
}

__global__ void k_dinv() {
    int n = blockIdx.x * blockDim.x + threadIdx.x;
    if (n < NN) g_dinv[n] = rsqrtf(g_deg[n]);        // deg >= 1 always
}

// exclusive scan of g_cnt -> g_rowptr (single block, 1024 threads, 4 items/thread)
__global__ void k_scan() {
    __shared__ int warpsum[32];
    int tid = threadIdx.x;
    int base = tid * 4;
    int v[4]; int s = 0;
    #pragma unroll
    for (int i = 0; i < 4; i++) {
        int c = (base + i < NN) ? g_cnt[base + i] : 0;
        v[i] = s; s += c;
    }
    int lane = tid & 31, wid = tid >> 5;
    int inc = s;
    #pragma unroll
    for (int o = 1; o < 32; o <<= 1) {
        int t2 = __shfl_up_sync(0xffffffffu, inc, o);
        if (lane >= o) inc += t2;
    }
    if (lane == 31) warpsum[wid] = inc;
    __syncthreads();
    if (wid == 0) {
        int ws = warpsum[lane];
        #pragma unroll
        for (int o = 1; o < 32; o <<= 1) {
            int t2 = __shfl_up_sync(0xffffffffu, ws, o);
            if (lane >= o) ws += t2;
        }
        warpsum[lane] = ws;
    }
    __syncthreads();
    int excl = inc - s + (wid ? warpsum[wid - 1] : 0);
    #pragma unroll
    for (int i = 0; i < 4; i++)
        if (base + i < NN) g_rowptr[base + i] = excl + v[i];
    if (tid == 1023) g_rowptr[NN] = excl + s;
}

__global__ void k_fill(const int* __restrict__ ei, const float* __restrict__ ew) {
    int e = blockIdx.x * blockDim.x + threadIdx.x;
    if (e < EE) {
        int sn = ei[e], dn = ei[EE + e];
        int pos = g_rowptr[dn] + atomicAdd(&g_fill[dn], 1);
        g_srcs[pos]  = sn;
        g_norms[pos] = g_dinv[sn] * ew[e] * g_dinv[dn];
    }
}

// ---------------- weight prep: fold W_ih|W_hh -> k-transposed float4 layout ----------------
__global__ void k_prepw(const float* __restrict__ Wih, const float* __restrict__ Whh,
                        const float* __restrict__ bih, const float* __restrict__ bhh) {
    int idx = blockIdx.x * blockDim.x + threadIdx.x;      // over G4*KTOT
    if (idx < G4 * KTOT) {
        int j = idx / KTOT, k = idx % KTOT;
        float v = (k < DD) ? Wih[j * DD + k] : Whh[j * HH + (k - DD)];
        int kk = k >> 2, l = k & 3;
        ((float*)g_WT4)[(size_t)(kk * G4 + j) * 4 + l] = v;
    }
    if (idx < G4) g_bsum[idx] = bih[idx] + bhh[idx];
}

// ---------------- GCN1 transform: hw1 = x @ W1  (14 -> 64) ----------------
__global__ __launch_bounds__(256) void k_gcn1(const float* __restrict__ x,
                                              const float* __restrict__ W1) {
    int d = threadIdx.x & 63;
    float wcol[FEAT];
    #pragma unroll
    for (int f = 0; f < FEAT; f++) wcol[f] = W1[f * DD + d];
    __shared__ float xs[4][FEAT];
    size_t totalRows = (size_t)TT * NN;                   // divisible by 4
    for (size_t r0 = (size_t)blockIdx.x * 4; r0 < totalRows; r0 += (size_t)gridDim.x * 4) {
        __syncthreads();
        if (threadIdx.x < 4 * FEAT)
            ((float*)xs)[threadIdx.x] = x[r0 * FEAT + threadIdx.x];
        __syncthreads();
        int rr = threadIdx.x >> 6;
        float acc = 0.0f;
        #pragma unroll
        for (int f = 0; f < FEAT; f++) acc = fmaf(xs[rr][f], wcol[f], acc);
        g_hw1[r0 * DD + threadIdx.x] = acc;
    }
}

// ---------------- fused layer-1 aggregation + relu + W2 transform ----------------
// Block = (node n, chunk of TC1 timesteps), 64 threads (thread = output dim d).
// hw2[t][n][:] = relu(agg1(hw1)[t][n][:] + b1) @ W2    (edge index loads amortized over TC1)
__global__ __launch_bounds__(64) void k_agg1f(const float* __restrict__ b1,
                                              const float* __restrict__ W2) {
    __shared__ __align__(16) float sh1[TC1][DD];
    int n = blockIdx.x, d = threadIdx.x;
    int t0 = blockIdx.y * TC1;
    const size_t plane = (size_t)NN * DD;
    const float* base = g_hw1 + (size_t)t0 * plane;

    float wcol[DD];                                   // W2 column d in registers
    #pragma unroll
    for (int k = 0; k < DD; k++) wcol[k] = __ldg(&W2[k * DD + d]);

    float di = g_dinv[n], sw = di * di;
    size_t no = (size_t)n * DD + d;
    float acc[TC1];
    #pragma unroll
    for (int tc = 0; tc < TC1; tc++) acc[tc] = sw * __ldg(base + (size_t)tc * plane + no);

    int s = g_rowptr[n], e = g_rowptr[n + 1];
    for (int i = s; i < e; i++) {
        int sn = g_srcs[i]; float w = g_norms[i];
        size_t o = (size_t)sn * DD + d;
        #pragma unroll
        for (int tc = 0; tc < TC1; tc++)
            acc[tc] = fmaf(w, __ldg(base + (size_t)tc * plane + o), acc[tc]);
    }
    float bv = b1[d];
    #pragma unroll
    for (int tc = 0; tc < TC1; tc++) sh1[tc][d] = fmaxf(acc[tc] + bv, 0.0f);
    __syncthreads();

    #pragma unroll
    for (int tc = 0; tc < TC1; tc++) {
        float a2 = 0.0f;
        #pragma unroll
        for (int k = 0; k < DD; k += 4) {
            float4 h4 = *(const float4*)&sh1[tc][k];
            a2 = fmaf(h4.x, wcol[k],     a2);
            a2 = fmaf(h4.y, wcol[k + 1], a2);
            a2 = fmaf(h4.z, wcol[k + 2], a2);
            a2 = fmaf(h4.w, wcol[k + 3], a2);
        }
        g_hw2[(size_t)(t0 + tc) * plane + no] = a2;
    }
}

// ---------------- layer-2 aggregation: emb = agg2(hw2) + b2 + county_bias ----------------
__global__ __launch_bounds__(64) void k_agg2(const float* __restrict__ b2,
                                             const float* __restrict__ cb) {
    int n = blockIdx.x, d = threadIdx.x;
    int t0 = blockIdx.y * TC2;
    const size_t plane = (size_t)NN * DD;
    const float* base = g_hw2 + (size_t)t0 * plane;
    float di = g_dinv[n], sw = di * di;
    size_t no = (size_t)n * DD + d;
    float acc[TC2];
    #pragma unroll
    for (int tc = 0; tc < TC2; tc++) acc[tc] = sw * __ldg(base + (size_t)tc * plane + no);
    int s = g_rowptr[n], e = g_rowptr[n + 1];
    for (int i = s; i < e; i++) {
        int sn = g_srcs[i]; float w = g_norms[i];
        size_t o = (size_t)sn * DD + d;
        #pragma unroll
        for (int tc = 0; tc < TC2; tc++)
            acc[tc] = fmaf(w, __ldg(base + (size_t)tc * plane + o), acc[tc]);
    }
    float add = b2[d] + __ldg(&cb[no]);
    #pragma unroll
    for (int tc = 0; tc < TC2; tc++)
        g_emb[(size_t)(t0 + tc) * plane + no] = acc[tc] + add;
}

// ---------------- persistent LSTM: FFMA2 (fp32x2) mainloop, state in shared ----------------
// Each accumulator is a packed {even-k, odd-k} partial-sum pair; lanes summed at gate time.
__global__ __launch_bounds__(256) void k_lstm() {
    __shared__ __align__(16) float a_s[MNODES][KTOT];   // [x(64) | h(128)] per node
    __shared__ float c_s[MNODES][HH];
    __shared__ float p_s[MNODES][HH];                   // sig(i)*tanh(g)

    int tid = threadIdx.x;
    int nb  = blockIdx.x * MNODES;
    int mcnt = min(MNODES, NN - nb);

    for (int i = tid; i < MNODES * KTOT; i += 256) ((float*)a_s)[i] = 0.0f;
    for (int i = tid; i < MNODES * HH;   i += 256) ((float*)c_s)[i] = 0.0f;

    float bias0 = g_bsum[tid];
    float bias1 = g_bsum[tid + 256];
    const ulonglong2* __restrict__ Wp = (const ulonglong2*)g_WT4;   // [kk*G4 + j]
    __syncthreads();

    for (int t = 0; t < TT; t++) {
        // load x_t tile (coalesced rows of embeds)
        const float* xin = g_emb + ((size_t)t * NN + nb) * DD;
        for (int i = tid; i < mcnt * DD; i += 256) {
            int m = i >> 6, f = i & 63;
            a_s[m][f] = xin[i];
        }
        __syncthreads();

        // G = bias + [x|h] @ Wcomb^T ; thread owns gate columns tid and tid+256
        unsigned long long acc0[MNODES], acc1[MNODES];
        #pragma unroll
        for (int m = 0; m < MNODES; m++) { acc0[m] = 0ull; acc1[m] = 0ull; }

        ulonglong2 w0 = Wp[tid];
        ulonglong2 w1 = Wp[tid + 256];
        #pragma unroll 1
        for (int kk = 0; kk < KTOT / 4; kk++) {
            int nk = (kk + 1 < KTOT / 4) ? kk + 1 : kk;   // prefetch next weights (L2-resident)
            ulonglong2 nw0 = Wp[nk * G4 + tid];
            ulonglong2 nw1 = Wp[nk * G4 + tid + 256];
            #pragma unroll
            for (int m = 0; m < MNODES; m++) {
                ulonglong2 av = *(const ulonglong2*)&a_s[m][kk * 4]; // broadcast LDS.128
                ffma2(acc0[m], av.x, w0.x);
                ffma2(acc1[m], av.x, w1.x);
                ffma2(acc0[m], av.y, w0.y);
                ffma2(acc1[m], av.y, w1.y);
            }
            w0 = nw0; w1 = nw1;
        }

        // gates: tid<128 holds (i_u, g_u); tid>=128 holds (f_u, o_u), u = tid&127
        float fo0[MNODES], fo1[MNODES];
        if (tid < 128) {
            int u = tid;
            #pragma unroll
            for (int m = 0; m < MNODES; m++) {
                float gi = pairsum(acc0[m]) + bias0;
                float gg = pairsum(acc1[m]) + bias1;
                p_s[m][u] = sigf(gi) * tanhf_fast(gg);
            }
        } else {
            #pragma unroll
            for (int m = 0; m < MNODES; m++) {       // independent of p_s: pre-barrier
                fo0[m] = sigf(pairsum(acc0[m]) + bias0);
                fo1[m] = sigf(pairsum(acc1[m]) + bias1);
            }
        }
        __syncthreads();   // also fences all a_s reads of the GEMM phase
        if (tid >= 128) {
            int u = tid - 128;
            #pragma unroll
            for (int m = 0; m < MNODES; m++) {
                float c = fmaf(fo0[m], c_s[m][u], p_s[m][u]);
                c_s[m][u] = c;
                a_s[m][DD + u] = fo1[m] * tanhf_fast(c);
            }
        }
        __syncthreads();
    }

    // write final hidden state
    for (int i = tid; i < mcnt * HH; i += 256) {
        int m = i >> 7, u = i & 127;
        g_hfinal[(size_t)(nb + m) * HH + u] = a_s[m][DD + u];
    }
}

// ---------------- head MLP: out = relu(hf @ Wm1 + bm1) @ Wm2 + bm2 ----------------
__global__ void k_head(const float* __restrict__ Wm1, const float* __restrict__ bm1,
                       const float* __restrict__ Wm2, const float* __restrict__ bm2,
                       float* __restrict__ out) {
    __shared__ float hrow[HH];
    __shared__ float zred[2];
    int n = blockIdx.x, d = threadIdx.x;
    for (int i = d; i < HH; i += 64) hrow[i] = g_hfinal[(size_t)n * HH + i];
    __syncthreads();
    float acc = bm1[d];
    #pragma unroll 8
    for (int k = 0; k < HH; k++) acc = fmaf(hrow[k], Wm1[k * 64 + d], acc);
    acc = fmaxf(acc, 0.0f) * Wm2[d];
    #pragma unroll
    for (int o = 16; o; o >>= 1) acc += __shfl_down_sync(0xffffffffu, acc, o);
    if ((d & 31) == 0) zred[d >> 5] = acc;
    __syncthreads();
    if (d == 0) out[n] = zred[0] + zred[1] + bm2[0];
}

// ---------------- launch ----------------
extern "C" void kernel_launch(void* const* d_in, const int* in_sizes, int n_in,
                              void* d_out, int out_size) {
    (void)in_sizes; (void)n_in; (void)out_size;
    const float* x    = (const float*)d_in[0];
    const int*   ei   = (const int*)  d_in[1];
    const float* ew   = (const float*)d_in[2];
    const float* W1   = (const float*)d_in[3];
    const float* b1   = (const float*)d_in[4];
    const float* W2   = (const float*)d_in[5];
    const float* b2   = (const float*)d_in[6];
    const float* cb   = (const float*)d_in[7];
    const float* Wih  = (const float*)d_in[8];
    const float* Whh  = (const float*)d_in[9];
    const float* bih  = (const float*)d_in[10];
    const float* bhh  = (const float*)d_in[11];
    const float* Wm1  = (const float*)d_in[12];
    const float* bm1  = (const float*)d_in[13];
    const float* Wm2  = (const float*)d_in[14];
    const float* bm2  = (const float*)d_in[15];
    float* out = (float*)d_out;

    k_init<<<(NN + 255) / 256, 256>>>();
    k_deg <<<(EE + 255) / 256, 256>>>(ei, ew);
    k_dinv<<<(NN + 255) / 256, 256>>>();
    k_scan<<<1, 1024>>>();
    k_fill<<<(EE + 255) / 256, 256>>>(ei, ew);
    k_prepw<<<(G4 * KTOT + 255) / 256, 256>>>(Wih, Whh, bih, bhh);

    k_gcn1<<<4096, 256>>>(x, W1);
    dim3 g1(NN, TT / TC1);
    k_agg1f<<<g1, 64>>>(b1, W2);
    dim3 g2(NN, TT / TC2);
    k_agg2<<<g2, 64>>>(b2, cb);

    k_lstm<<<NBLK, 256>>>();
    k_head<<<NN, 64>>>(Wm1, bm1, Wm2, bm2, out);
}

// round 10
// speedup vs baseline: 2.5383x; 2.5383x over previous
#include <cuda_runtime.h>
#include <cuda_bf16.h>
#include <cstddef>
#include <cstdint>

// ---------------- problem constants ----------------
#define TT   336
#define NN   3233
#define EE   20000
#define FEAT 14
#define DD   64
#define HH   128
#define G4   512
#define KTOT 192
#define MNODES 22
#define NBLK 147
#define NTP  24            // padded node tile (3 n-tiles of 8)
#define NKT  12            // k-tiles of 16
#define SBROW 400          // B row stride bytes (bank-spread)

// fragment-ordered W: [w][kt][mt][lane][reg] -> 8*12*4*32*4 = 49152 uint32
#define NFRAG 49152
#define WSM_BYTES (NFRAG * 4)          // 196608 B of W_hi in SMEM
#define SM_BH  WSM_BYTES               // B_hi: 24 x 400
#define SM_BL  (SM_BH + NTP * SBROW)
#define SM_TOTAL (SM_BL + NTP * SBROW)   // 215808 B

// ---------------- device scratch ----------------
__device__ float g_deg[NN];
__device__ float g_dinv[NN];
__device__ int   g_cnt[NN];
__device__ int   g_fill[NN];
__device__ int   g_rowptr[NN + 1];
__device__ int   g_srcs[EE];
__device__ float g_norms[EE];

__device__ float g_hw1[(size_t)TT * NN * DD];
__device__ float g_h1 [(size_t)TT * NN * DD];
__device__ float g_hw2[(size_t)TT * NN * DD];
__device__ float g_emb[(size_t)TT * NN * DD];
__device__ float g_hfinal[NN * HH];

__device__ uint32_t g_WhiF[NFRAG];   // bf16x2 hi fragments
__device__ uint32_t g_WloF[NFRAG];   // bf16x2 lo fragments

// ---------------- activations ----------------
__device__ __forceinline__ float sigf(float x) {
    return __fdividef(1.0f, 1.0f + __expf(-x));
}
__device__ __forceinline__ float tanhf_fast(float x) {
    return 2.0f * sigf(2.0f * x) - 1.0f;
}

// ---------------- warp mma (bf16 -> fp32), sm_80+ path ----------------
__device__ __forceinline__ void mma_bf16(float* c, uint32_t a0, uint32_t a1,
                                         uint32_t a2, uint32_t a3,
                                         uint32_t b0, uint32_t b1) {
    asm volatile("mma.sync.aligned.m16n8k16.row.col.f32.bf16.bf16.f32 "
                 "{%0,%1,%2,%3},{%4,%5,%6,%7},{%8,%9},{%0,%1,%2,%3};"
                 : "+f"(c[0]), "+f"(c[1]), "+f"(c[2]), "+f"(c[3])
                 : "r"(a0), "r"(a1), "r"(a2), "r"(a3), "r"(b0), "r"(b1));
}

// ---------------- graph prep (known-good) ----------------
__global__ void k_init() {
    int n = blockIdx.x * blockDim.x + threadIdx.x;
    if (n < NN) { g_deg[n] = 1.0f; g_cnt[n] = 0; g_fill[n] = 0; }
}
__global__ void k_deg(const int* __restrict__ ei, const float* __restrict__ ew) {
    int e = blockIdx.x * blockDim.x + threadIdx.x;
    if (e < EE) {
        int dn = ei[EE + e];
        atomicAdd(&g_deg[dn], ew[e]);
        atomicAdd(&g_cnt[dn], 1);
    }
}
__global__ void k_dinv() {
    int n = blockIdx.x * blockDim.x + threadIdx.x;
    if (n < NN) g_dinv[n] = rsqrtf(g_deg[n]);
}
__global__ void k_scan() {
    __shared__ int warpsum[32];
    int tid = threadIdx.x;
    int base = tid * 4;
    int v[4]; int s = 0;
    #pragma unroll
    for (int i = 0; i < 4; i++) {
        int c = (base + i < NN) ? g_cnt[base + i] : 0;
        v[i] = s; s += c;
    }
    int lane = tid & 31, wid = tid >> 5;
    int inc = s;
    #pragma unroll
    for (int o = 1; o < 32; o <<= 1) {
        int t2 = __shfl_up_sync(0xffffffffu, inc, o);
        if (lane >= o) inc += t2;
    }
    if (lane == 31) warpsum[wid] = inc;
    __syncthreads();
    if (wid == 0) {
        int ws = warpsum[lane];
        #pragma unroll
        for (int o = 1; o < 32; o <<= 1) {
            int t2 = __shfl_up_sync(0xffffffffu, ws, o);
            if (lane >= o) ws += t2;
        }
        warpsum[lane] = ws;
    }
    __syncthreads();
    int excl = inc - s + (wid ? warpsum[wid - 1] : 0);
    #pragma unroll
    for (int i = 0; i < 4; i++)
        if (base + i < NN) g_rowptr[base + i] = excl + v[i];
    if (tid == 1023) g_rowptr[NN] = excl + s;
}
__global__ void k_fill(const int* __restrict__ ei, const float* __restrict__ ew) {
    int e = blockIdx.x * blockDim.x + threadIdx.x;
    if (e < EE) {
        int sn = ei[e], dn = ei[EE + e];
        int pos = g_rowptr[dn] + atomicAdd(&g_fill[dn], 1);
        g_srcs[pos]  = sn;
        g_norms[pos] = g_dinv[sn] * ew[e] * g_dinv[dn];
    }
}

// ---------------- W fragment prep ----------------
// Gate-row permutation: warp w, m-tile mt, local row r (0..15):
//   gate = r/4 (i,f,g,o), unit = 16w + 4mt + r%4, orig row = gate*128 + unit.
// Fragment idx layout: (((w*12 + kt)*4 + mt)*32 + lane)*4 + reg, each reg = bf16x2 (k, k+1).
__global__ void k_prepw(const float* __restrict__ Wih, const float* __restrict__ Whh) {
    int idx = blockIdx.x * blockDim.x + threadIdx.x;
    if (idx >= NFRAG) return;
    int reg  = idx & 3;
    int lane = (idx >> 2) & 31;
    int mt   = (idx >> 7) & 3;
    int kt   = (idx >> 9) % 12;
    int w    = idx / 6144;
    int gid = lane >> 2, tig = lane & 3;
    int r = ((reg == 0 || reg == 2) ? gid : gid + 8);
    int k = 16 * kt + tig * 2 + ((reg >= 2) ? 8 : 0);
    int row = (r >> 2) * 128 + 16 * w + 4 * mt + (r & 3);
    float v0 = (k     < DD) ? Wih[row * DD + k]       : Whh[row * HH + (k - DD)];
    float v1 = (k + 1 < DD) ? Wih[row * DD + k + 1]   : Whh[row * HH + (k + 1 - DD)];
    __nv_bfloat16 h0 = __float2bfloat16(v0), h1 = __float2bfloat16(v1);
    __nv_bfloat16 l0 = __float2bfloat16(v0 - __bfloat162float(h0));
    __nv_bfloat16 l1 = __float2bfloat16(v1 - __bfloat162float(h1));
    g_WhiF[idx] = (uint32_t)__bfloat16_as_ushort(h0) | ((uint32_t)__bfloat16_as_ushort(h1) << 16);
    g_WloF[idx] = (uint32_t)__bfloat16_as_ushort(l0) | ((uint32_t)__bfloat16_as_ushort(l1) << 16);
}

// ---------------- GCN stages (exact 9085us-baseline code) ----------------
__global__ __launch_bounds__(256) void k_gcn1(const float* __restrict__ x,
                                              const float* __restrict__ W1) {
    int d = threadIdx.x & 63;
    float wcol[FEAT];
    #pragma unroll
    for (int f = 0; f < FEAT; f++) wcol[f] = W1[f * DD + d];
    __shared__ float xs[4][FEAT];
    size_t totalRows = (size_t)TT * NN;
    for (size_t r0 = (size_t)blockIdx.x * 4; r0 < totalRows; r0 += (size_t)gridDim.x * 4) {
        __syncthreads();
        if (threadIdx.x < 4 * FEAT)
            ((float*)xs)[threadIdx.x] = x[r0 * FEAT + threadIdx.x];
        __syncthreads();
        int rr = threadIdx.x >> 6;
        float acc = 0.0f;
        #pragma unroll
        for (int f = 0; f < FEAT; f++) acc = fmaf(xs[rr][f], wcol[f], acc);
        g_hw1[r0 * DD + threadIdx.x] = acc;
    }
}
__global__ __launch_bounds__(256) void k_gcn2(const float* __restrict__ W2) {
    int d = threadIdx.x & 63;
    float wcol[DD];
    #pragma unroll
    for (int f = 0; f < DD; f++) wcol[f] = W2[f * DD + d];
    __shared__ __align__(16) float rows[4][DD];
    size_t totalRows = (size_t)TT * NN;
    for (size_t r0 = (size_t)blockIdx.x * 4; r0 < totalRows; r0 += (size_t)gridDim.x * 4) {
        __syncthreads();
        ((float*)rows)[threadIdx.x] = g_h1[r0 * DD + threadIdx.x];
        __syncthreads();
        int rr = threadIdx.x >> 6;
        float acc = 0.0f;
        #pragma unroll
        for (int f = 0; f < DD; f += 4) {
            float4 a = *(const float4*)&rows[rr][f];
            acc = fmaf(a.x, wcol[f],     acc);
            acc = fmaf(a.y, wcol[f + 1], acc);
            acc = fmaf(a.z, wcol[f + 2], acc);
            acc = fmaf(a.w, wcol[f + 3], acc);
        }
        g_hw2[r0 * DD + threadIdx.x] = acc;
    }
}
__global__ void k_agg(int layer, const float* __restrict__ b, const float* __restrict__ cb) {
    int n = blockIdx.x, t0 = blockIdx.y * 2, d = threadIdx.x;
    const float* hw = (layer == 1) ? g_hw1 : g_hw2;
    const float* hwt0 = hw + (size_t)t0 * NN * DD;
    const float* hwt1 = hwt0 + (size_t)NN * DD;
    float di = g_dinv[n];
    float sw = di * di;
    float acc0 = sw * __ldg(&hwt0[(size_t)n * DD + d]);
    float acc1 = sw * __ldg(&hwt1[(size_t)n * DD + d]);
    int s = g_rowptr[n], e = g_rowptr[n + 1];
    for (int i = s; i < e; i++) {
        int    sn = g_srcs[i];
        float  w  = g_norms[i];
        size_t o  = (size_t)sn * DD + d;
        acc0 = fmaf(w, __ldg(&hwt0[o]), acc0);
        acc1 = fmaf(w, __ldg(&hwt1[o]), acc1);
    }
    float bv = b[d];
    acc0 += bv; acc1 += bv;
    float* o;
    if (layer == 1) {
        acc0 = fmaxf(acc0, 0.0f); acc1 = fmaxf(acc1, 0.0f); o = g_h1;
    } else {
        float cbv = cb[(size_t)n * DD + d];
        acc0 += cbv; acc1 += cbv; o = g_emb;
    }
    o[((size_t)t0 * NN + n) * DD + d] = acc0;
    o[((size_t)(t0 + 1) * NN + n) * DD + d] = acc1;
}

// ---------------- persistent LSTM on mma.sync bf16 (3-term split precision) ----------------
// Per CTA: 22 nodes (padded 24). gates[512 x 24] = W[512 x 192] . B[24 x 192]^T per step.
// W_hi fragments in SMEM (LDS.128); W_lo fragments streamed from L2 (LDG.128).
// Warp w owns units 16w..16w+15: each m-tile = 4 units x gates {i,f,g,o} -> epilogue
// needs only a shfl_xor(16) to pair (i,g) with (f,o) threads.
__global__ __launch_bounds__(256, 1) void k_lstm_mma(const float* __restrict__ bih,
                                                     const float* __restrict__ bhh) {
    extern __shared__ char smem[];
    int tid = threadIdx.x;
    int w = tid >> 5, lane = tid & 31;
    int gid = lane >> 2, tig = lane & 3, q = gid & 3;
    int nb = blockIdx.x * MNODES;
    int mcnt = min(MNODES, NN - nb);

    // ---- init: W_hi -> SMEM, zero B regions
    {
        const uint4* src = (const uint4*)g_WhiF;
        uint4* dst = (uint4*)smem;
        for (int i = tid; i < WSM_BYTES / 16; i += 256) dst[i] = __ldg(&src[i]);
        uint32_t* bz = (uint32_t*)(smem + SM_BH);
        for (int i = tid; i < (2 * NTP * SBROW) / 4; i += 256) bz[i] = 0u;
    }
    // biases for this thread's gate rows: biasA = gate (i|f), biasB = gate (g|o)
    int gA = gid >> 2;                    // 0: low half (i,g); 1: high half (f,o)
    float biasA[4], biasB[4];
    #pragma unroll
    for (int mt = 0; mt < 4; mt++) {
        int unit = 16 * w + 4 * mt + q;
        biasA[mt] = bih[gA * 128 + unit] + bhh[gA * 128 + unit];
        biasB[mt] = bih[(gA + 2) * 128 + unit] + bhh[(gA + 2) * 128 + unit];
    }
    // x(0) -> B
    {
        const float* xin = g_emb + (size_t)nb * DD;
        for (int j = 0; j < 6; j++) {
            int idx = tid + 256 * j;
            if (idx < mcnt * DD) {
                int n = idx >> 6, k = idx & 63;
                float v = xin[idx];
                __nv_bfloat16 hi = __float2bfloat16(v);
                __nv_bfloat16 lo = __float2bfloat16(v - __bfloat162float(hi));
                *(__nv_bfloat16*)(smem + SM_BH + n * SBROW + 2 * k) = hi;
                *(__nv_bfloat16*)(smem + SM_BL + n * SBROW + 2 * k) = lo;
            }
        }
    }
    __syncthreads();

    float cst[4][3][2];
    #pragma unroll
    for (int mt = 0; mt < 4; mt++)
        #pragma unroll
        for (int nt = 0; nt < 3; nt++) { cst[mt][nt][0] = 0.0f; cst[mt][nt][1] = 0.0f; }

    const uint4* gWlo = (const uint4*)g_WloF;
    const char* smw = smem + w * (NKT * 4 * 32 * 16);   // this warp's W_hi slice

    for (int t = 0; t < TT; t++) {
        // prefetch x(t+1) (global, latency hidden under mma phase)
        float xv[6];
        if (t + 1 < TT) {
            const float* xin = g_emb + ((size_t)(t + 1) * NN + nb) * DD;
            #pragma unroll
            for (int j = 0; j < 6; j++) {
                int idx = tid + 256 * j;
                xv[j] = (idx < mcnt * DD) ? __ldg(&xin[idx]) : 0.0f;
            }
        }

        // ---- mma mainloop
        float acc[4][3][4];
        #pragma unroll
        for (int mt = 0; mt < 4; mt++)
            #pragma unroll
            for (int nt = 0; nt < 3; nt++)
                #pragma unroll
                for (int r = 0; r < 4; r++) acc[mt][nt][r] = 0.0f;

        #pragma unroll 2
        for (int kt = 0; kt < NKT; kt++) {
            uint32_t bh0[3], bh1[3], bl0[3], bl1[3];
            #pragma unroll
            for (int nt = 0; nt < 3; nt++) {
                int boffs = (nt * 8 + gid) * SBROW + (kt * 16 + tig * 2) * 2;
                bh0[nt] = *(const uint32_t*)(smem + SM_BH + boffs);
                bh1[nt] = *(const uint32_t*)(smem + SM_BH + boffs + 16);
                bl0[nt] = *(const uint32_t*)(smem + SM_BL + boffs);
                bl1[nt] = *(const uint32_t*)(smem + SM_BL + boffs + 16);
            }
            #pragma unroll
            for (int mt = 0; mt < 4; mt++) {
                uint4 ah = *(const uint4*)(smw + ((kt * 4 + mt) * 32 + lane) * 16);
                uint4 al = __ldg(&gWlo[((w * NKT + kt) * 4 + mt) * 32 + lane]);
                #pragma unroll
                for (int nt = 0; nt < 3; nt++) {
                    mma_bf16(acc[mt][nt], ah.x, ah.y, ah.z, ah.w, bh0[nt], bh1[nt]);
                    mma_bf16(acc[mt][nt], ah.x, ah.y, ah.z, ah.w, bl0[nt], bl1[nt]);
                    mma_bf16(acc[mt][nt], al.x, al.y, al.z, al.w, bh0[nt], bh1[nt]);
                }
            }
        }
        __syncthreads();   // all B reads complete before anyone rewrites B

        // ---- epilogue: low threads (gid<4) hold (i,g); high threads (f,o) + state
        #pragma unroll
        for (int mt = 0; mt < 4; mt++) {
            #pragma unroll
            for (int nt = 0; nt < 3; nt++) {
                float vA0 = acc[mt][nt][0] + biasA[mt];
                float vA1 = acc[mt][nt][1] + biasA[mt];
                float vB0 = acc[mt][nt][2] + biasB[mt];
                float vB1 = acc[mt][nt][3] + biasB[mt];
                // low-half interpretation: p = sig(i)*tanh(g)
                float p0 = sigf(vA0) * tanhf_fast(vB0);
                float p1 = sigf(vA1) * tanhf_fast(vB1);
                float q0 = __shfl_xor_sync(0xffffffffu, p0, 16);
                float q1 = __shfl_xor_sync(0xffffffffu, p1, 16);
                if (gA) {   // high half: f,o + state update
                    float f0 = sigf(vA0), f1 = sigf(vA1);
                    float o0 = sigf(vB0), o1 = sigf(vB1);
                    float c0 = fmaf(f0, cst[mt][nt][0], q0);
                    float c1 = fmaf(f1, cst[mt][nt][1], q1);
                    cst[mt][nt][0] = c0; cst[mt][nt][1] = c1;
                    float h0 = o0 * tanhf_fast(c0);
                    float h1 = o1 * tanhf_fast(c1);
                    int unit = 16 * w + 4 * mt + q;
                    int n0 = nt * 8 + tig * 2, n1 = n0 + 1;
                    if (n0 < mcnt) {
                        __nv_bfloat16 hi = __float2bfloat16(h0);
                        __nv_bfloat16 lo = __float2bfloat16(h0 - __bfloat162float(hi));
                        *(__nv_bfloat16*)(smem + SM_BH + n0 * SBROW + (DD + unit) * 2) = hi;
                        *(__nv_bfloat16*)(smem + SM_BL + n0 * SBROW + (DD + unit) * 2) = lo;
                        if (t == TT - 1) g_hfinal[(size_t)(nb + n0) * HH + unit] = h0;
                    }
                    if (n1 < mcnt) {
                        __nv_bfloat16 hi = __float2bfloat16(h1);
                        __nv_bfloat16 lo = __float2bfloat16(h1 - __bfloat162float(hi));
                        *(__nv_bfloat16*)(smem + SM_BH + n1 * SBROW + (DD + unit) * 2) = hi;
                        *(__nv_bfloat16*)(smem + SM_BL + n1 * SBROW + (DD + unit) * 2) = lo;
                        if (t == TT - 1) g_hfinal[(size_t)(nb + n1) * HH + unit] = h1;
                    }
                }
            }
        }
        // store x(t+1)
        if (t + 1 < TT) {
            #pragma unroll
            for (int j = 0; j < 6; j++) {
                int idx = tid + 256 * j;
                if (idx < mcnt * DD) {
                    int n = idx >> 6, k = idx & 63;
                    float v = xv[j];
                    __nv_bfloat16 hi = __float2bfloat16(v);
                    __nv_bfloat16 lo = __float2bfloat16(v - __bfloat162float(hi));
                    *(__nv_bfloat16*)(smem + SM_BH + n * SBROW + 2 * k) = hi;
                    *(__nv_bfloat16*)(smem + SM_BL + n * SBROW + 2 * k) = lo;
                }
            }
        }
        __syncthreads();   // B writes visible before next mainloop
    }
}

// ---------------- head MLP ----------------
__global__ void k_head(const float* __restrict__ Wm1, const float* __restrict__ bm1,
                       const float* __restrict__ Wm2, const float* __restrict__ bm2,
                       float* __restrict__ out) {
    __shared__ float hrow[HH];
    __shared__ float zred[2];
    int n = blockIdx.x, d = threadIdx.x;
    for (int i = d; i < HH; i += 64) hrow[i] = g_hfinal[(size_t)n * HH + i];
    __syncthreads();
    float acc = bm1[d];
    #pragma unroll 8
    for (int k = 0; k < HH; k++) acc = fmaf(hrow[k], Wm1[k * 64 + d], acc);
    acc = fmaxf(acc, 0.0f) * Wm2[d];
    #pragma unroll
    for (int o = 16; o; o >>= 1) acc += __shfl_down_sync(0xffffffffu, acc, o);
    if ((d & 31) == 0) zred[d >> 5] = acc;
    __syncthreads();
    if (d == 0) out[n] = zred[0] + zred[1] + bm2[0];
}

// ---------------- launch ----------------
extern "C" void kernel_launch(void* const* d_in, const int* in_sizes, int n_in,
                              void* d_out, int out_size) {
    (void)in_sizes; (void)n_in; (void)out_size;
    const float* x    = (const float*)d_in[0];
    const int*   ei   = (const int*)  d_in[1];
    const float* ew   = (const float*)d_in[2];
    const float* W1   = (const float*)d_in[3];
    const float* b1   = (const float*)d_in[4];
    const float* W2   = (const float*)d_in[5];
    const float* b2   = (const float*)d_in[6];
    const float* cb   = (const float*)d_in[7];
    const float* Wih  = (const float*)d_in[8];
    const float* Whh  = (const float*)d_in[9];
    const float* bih  = (const float*)d_in[10];
    const float* bhh  = (const float*)d_in[11];
    const float* Wm1  = (const float*)d_in[12];
    const float* bm1  = (const float*)d_in[13];
    const float* Wm2  = (const float*)d_in[14];
    const float* bm2  = (const float*)d_in[15];
    float* out = (float*)d_out;

    cudaFuncSetAttribute(k_lstm_mma, cudaFuncAttributeMaxDynamicSharedMemorySize, SM_TOTAL);

    k_init<<<(NN + 255) / 256, 256>>>();
    k_deg <<<(EE + 255) / 256, 256>>>(ei, ew);
    k_dinv<<<(NN + 255) / 256, 256>>>();
    k_scan<<<1, 1024>>>();
    k_fill<<<(EE + 255) / 256, 256>>>(ei, ew);
    k_prepw<<<NFRAG / 256, 256>>>(Wih, Whh);

    k_gcn1<<<4096, 256>>>(x, W1);
    dim3 aggGrid(NN, TT / 2);
    k_agg<<<aggGrid, 64>>>(1, b1, nullptr);
    k_gcn2<<<4096, 256>>>(W2);
    k_agg<<<aggGrid, 64>>>(2, b2, cb);

    k_lstm_mma<<<NBLK, 256, SM_TOTAL>>>(bih, bhh);
    k_head<<<NN, 64>>>(Wm1, bm1, Wm2, bm2, out);
}

// round 12
// speedup vs baseline: 2.9359x; 1.1566x over previous
#include <cuda_runtime.h>
#include <cuda_fp16.h>
#include <cstddef>
#include <cstdint>

// ---------------- problem constants ----------------
#define TT   336
#define NN   3233
#define EE   20000
#define FEAT 14
#define DD   64
#define HH   128
#define G4   512
#define KTOT 192
#define MNODES 22
#define NBLK 147
#define NTP  24            // padded node tile (3 n-tiles of 8)
#define NKT  12            // k-tiles of 16
#define SBROW 400          // B row stride bytes (bank-spread)

// fragment-ordered W: [w][kt][mt][lane][reg] -> 8*12*4*32*4 = 49152 uint32
#define NFRAG 49152
#define WSM_BYTES (NFRAG * 4)          // 196608 B of W_hi in SMEM
#define SM_BH  WSM_BYTES               // B: 24 x 400 (single fp16 operand)
#define SM_TOTAL (SM_BH + NTP * SBROW)   // 206208 B

// ---------------- device scratch ----------------
__device__ float g_deg[NN];
__device__ float g_dinv[NN];
__device__ int   g_cnt[NN];
__device__ int   g_fill[NN];
__device__ int   g_rowptr[NN + 1];
__device__ int   g_srcs[EE];
__device__ float g_norms[EE];

__device__ float g_hw1[(size_t)TT * NN * DD];
__device__ float g_h1 [(size_t)TT * NN * DD];
__device__ float g_hw2[(size_t)TT * NN * DD];
__device__ float g_emb[(size_t)TT * NN * DD];
__device__ float g_hfinal[NN * HH];

__device__ uint32_t g_WhiF[NFRAG];   // f16x2 hi fragments
__device__ uint32_t g_WloF[NFRAG];   // f16x2 lo (residual) fragments

// ---------------- activations ----------------
__device__ __forceinline__ float sigf(float x) {
    return __fdividef(1.0f, 1.0f + __expf(-x));
}
__device__ __forceinline__ float tanhf_fast(float x) {
    return 2.0f * sigf(2.0f * x) - 1.0f;
}

// ---------------- warp mma (fp16 -> fp32), sm_80+ path ----------------
__device__ __forceinline__ void mma_f16(float* c, uint32_t a0, uint32_t a1,
                                        uint32_t a2, uint32_t a3,
                                        uint32_t b0, uint32_t b1) {
    asm volatile("mma.sync.aligned.m16n8k16.row.col.f32.f16.f16.f32 "
                 "{%0,%1,%2,%3},{%4,%5,%6,%7},{%8,%9},{%0,%1,%2,%3};"
                 : "+f"(c[0]), "+f"(c[1]), "+f"(c[2]), "+f"(c[3])
                 : "r"(a0), "r"(a1), "r"(a2), "r"(a3), "r"(b0), "r"(b1));
}

// ---------------- graph prep (known-good) ----------------
__global__ void k_init() {
    int n = blockIdx.x * blockDim.x + threadIdx.x;
    if (n < NN) { g_deg[n] = 1.0f; g_cnt[n] = 0; g_fill[n] = 0; }
}
__global__ void k_deg(const int* __restrict__ ei, const float* __restrict__ ew) {
    int e = blockIdx.x * blockDim.x + threadIdx.x;
    if (e < EE) {
        int dn = ei[EE + e];
        atomicAdd(&g_deg[dn], ew[e]);
        atomicAdd(&g_cnt[dn], 1);
    }
}
__global__ void k_dinv() {
    int n = blockIdx.x * blockDim.x + threadIdx.x;
    if (n < NN) g_dinv[n] = rsqrtf(g_deg[n]);
}
__global__ void k_scan() {
    __shared__ int warpsum[32];
    int tid = threadIdx.x;
    int base = tid * 4;
    int v[4]; int s = 0;
    #pragma unroll
    for (int i = 0; i < 4; i++) {
        int c = (base + i < NN) ? g_cnt[base + i] : 0;
        v[i] = s; s += c;
    }
    int lane = tid & 31, wid = tid >> 5;
    int inc = s;
    #pragma unroll
    for (int o = 1; o < 32; o <<= 1) {
        int t2 = __shfl_up_sync(0xffffffffu, inc, o);
        if (lane >= o) inc += t2;
    }
    if (lane == 31) warpsum[wid] = inc;
    __syncthreads();
    if (wid == 0) {
        int ws = warpsum[lane];
        #pragma unroll
        for (int o = 1; o < 32; o <<= 1) {
            int t2 = __shfl_up_sync(0xffffffffu, ws, o);
            if (lane >= o) ws += t2;
        }
        warpsum[lane] = ws;
    }
    __syncthreads();
    int excl = inc - s + (wid ? warpsum[wid - 1] : 0);
    #pragma unroll
    for (int i = 0; i < 4; i++)
        if (base + i < NN) g_rowptr[base + i] = excl + v[i];
    if (tid == 1023) g_rowptr[NN] = excl + s;
}
__global__ void k_fill(const int* __restrict__ ei, const float* __restrict__ ew) {
    int e = blockIdx.x * blockDim.x + threadIdx.x;
    if (e < EE) {
        int sn = ei[e], dn = ei[EE + e];
        int pos = g_rowptr[dn] + atomicAdd(&g_fill[dn], 1);
        g_srcs[pos]  = sn;
        g_norms[pos] = g_dinv[sn] * ew[e] * g_dinv[dn];
    }
}

// ---------------- W fragment prep (fp16 hi + fp16 residual) ----------------
// Gate-row permutation: warp w, m-tile mt, local row r (0..15):
//   gate = r/4 (i,f,g,o), unit = 16w + 4mt + r%4, orig row = gate*128 + unit.
// Fragment idx layout: (((w*12 + kt)*4 + mt)*32 + lane)*4 + reg, each reg = f16x2 (k, k+1).
__global__ void k_prepw(const float* __restrict__ Wih, const float* __restrict__ Whh) {
    int idx = blockIdx.x * blockDim.x + threadIdx.x;
    if (idx >= NFRAG) return;
    int reg  = idx & 3;
    int lane = (idx >> 2) & 31;
    int mt   = (idx >> 7) & 3;
    int kt   = (idx >> 9) % 12;
    int w    = idx / 6144;
    int gid = lane >> 2, tig = lane & 3;
    int r = ((reg == 0 || reg == 2) ? gid : gid + 8);
    int k = 16 * kt + tig * 2 + ((reg >= 2) ? 8 : 0);
    int row = (r >> 2) * 128 + 16 * w + 4 * mt + (r & 3);
    float v0 = (k     < DD) ? Wih[row * DD + k]       : Whh[row * HH + (k - DD)];
    float v1 = (k + 1 < DD) ? Wih[row * DD + k + 1]   : Whh[row * HH + (k + 1 - DD)];
    __half h0 = __float2half_rn(v0), h1 = __float2half_rn(v1);
    __half l0 = __float2half_rn(v0 - __half2float(h0));
    __half l1 = __float2half_rn(v1 - __half2float(h1));
    g_WhiF[idx] = (uint32_t)__half_as_ushort(h0) | ((uint32_t)__half_as_ushort(h1) << 16);
    g_WloF[idx] = (uint32_t)__half_as_ushort(l0) | ((uint32_t)__half_as_ushort(l1) << 16);
}

// ---------------- GCN stages (exact 9085us-baseline code) ----------------
__global__ __launch_bounds__(256) void k_gcn1(const float* __restrict__ x,
                                              const float* __restrict__ W1) {
    int d = threadIdx.x & 63;
    float wcol[FEAT];
    #pragma unroll
    for (int f = 0; f < FEAT; f++) wcol[f] = W1[f * DD + d];
    __shared__ float xs[4][FEAT];
    size_t totalRows = (size_t)TT * NN;
    for (size_t r0 = (size_t)blockIdx.x * 4; r0 < totalRows; r0 += (size_t)gridDim.x * 4) {
        __syncthreads();
        if (threadIdx.x < 4 * FEAT)
            ((float*)xs)[threadIdx.x] = x[r0 * FEAT + threadIdx.x];
        __syncthreads();
        int rr = threadIdx.x >> 6;
        float acc = 0.0f;
        #pragma unroll
        for (int f = 0; f < FEAT; f++) acc = fmaf(xs[rr][f], wcol[f], acc);
        g_hw1[r0 * DD + threadIdx.x] = acc;
    }
}
__global__ __launch_bounds__(256) void k_gcn2(const float* __restrict__ W2) {
    int d = threadIdx.x & 63;
    float wcol[DD];
    #pragma unroll
    for (int f = 0; f < DD; f++) wcol[f] = W2[f * DD + d];
    __shared__ __align__(16) float rows[4][DD];
    size_t totalRows = (size_t)TT * NN;
    for (size_t r0 = (size_t)blockIdx.x * 4; r0 < totalRows; r0 += (size_t)gridDim.x * 4) {
        __syncthreads();
        ((float*)rows)[threadIdx.x] = g_h1[r0 * DD + threadIdx.x];
        __syncthreads();
        int rr = threadIdx.x >> 6;
        float acc = 0.0f;
        #pragma unroll
        for (int f = 0; f < DD; f += 4) {
            float4 a = *(const float4*)&rows[rr][f];
            acc = fmaf(a.x, wcol[f],     acc);
            acc = fmaf(a.y, wcol[f + 1], acc);
            acc = fmaf(a.z, wcol[f + 2], acc);
            acc = fmaf(a.w, wcol[f + 3], acc);
        }
        g_hw2[r0 * DD + threadIdx.x] = acc;
    }
}
__global__ void k_agg(int layer, const float* __restrict__ b, const float* __restrict__ cb) {
    int n = blockIdx.x, t0 = blockIdx.y * 2, d = threadIdx.x;
    const float* hw = (layer == 1) ? g_hw1 : g_hw2;
    const float* hwt0 = hw + (size_t)t0 * NN * DD;
    const float* hwt1 = hwt0 + (size_t)NN * DD;
    float di = g_dinv[n];
    float sw = di * di;
    float acc0 = sw * __ldg(&hwt0[(size_t)n * DD + d]);
    float acc1 = sw * __ldg(&hwt1[(size_t)n * DD + d]);
    int s = g_rowptr[n], e = g_rowptr[n + 1];
    for (int i = s; i < e; i++) {
        int    sn = g_srcs[i];
        float  w  = g_norms[i];
        size_t o  = (size_t)sn * DD + d;
        acc0 = fmaf(w, __ldg(&hwt0[o]), acc0);
        acc1 = fmaf(w, __ldg(&hwt1[o]), acc1);
    }
    float bv = b[d];
    acc0 += bv; acc1 += bv;
    float* o;
    if (layer == 1) {
        acc0 = fmaxf(acc0, 0.0f); acc1 = fmaxf(acc1, 0.0f); o = g_h1;
    } else {
        float cbv = cb[(size_t)n * DD + d];
        acc0 += cbv; acc1 += cbv; o = g_emb;
    }
    o[((size_t)t0 * NN + n) * DD + d] = acc0;
    o[((size_t)(t0 + 1) * NN + n) * DD + d] = acc1;
}

// ---------------- persistent LSTM on mma.sync fp16 (2-term split precision) ----------------
// gates[512 x 24] = W[512 x 192] . B[24 x 192]^T per step, W = W_hi + W_lo (both fp16,
// residual split => W represented to ~2^-22), B single fp16 (repr err ~2^-11, final ~1e-4).
// W_hi fragments in SMEM (LDS.128); W_lo fragments streamed from L2 (LDG.128).
// Warp w owns units 16w..16w+15: each m-tile = 4 units x gates {i,f,g,o} -> epilogue
// needs only a shfl_xor(16) to pair (i,g) with (f,o) threads.
__global__ __launch_bounds__(256, 1) void k_lstm_mma(const float* __restrict__ bih,
                                                     const float* __restrict__ bhh) {
    extern __shared__ char smem[];
    int tid = threadIdx.x;
    int w = tid >> 5, lane = tid & 31;
    int gid = lane >> 2, tig = lane & 3, q = gid & 3;
    int nb = blockIdx.x * MNODES;
    int mcnt = min(MNODES, NN - nb);

    // ---- init: W_hi -> SMEM, zero B region
    {
        const uint4* src = (const uint4*)g_WhiF;
        uint4* dst = (uint4*)smem;
        for (int i = tid; i < WSM_BYTES / 16; i += 256) dst[i] = __ldg(&src[i]);
        uint32_t* bz = (uint32_t*)(smem + SM_BH);
        for (int i = tid; i < (NTP * SBROW) / 4; i += 256) bz[i] = 0u;
    }
    // biases for this thread's gate rows: biasA = gate (i|f), biasB = gate (g|o)
    int gA = gid >> 2;                    // 0: low half (i,g); 1: high half (f,o)
    float biasA[4], biasB[4];
    #pragma unroll
    for (int mt = 0; mt < 4; mt++) {
        int unit = 16 * w + 4 * mt + q;
        biasA[mt] = bih[gA * 128 + unit] + bhh[gA * 128 + unit];
        biasB[mt] = bih[(gA + 2) * 128 + unit] + bhh[(gA + 2) * 128 + unit];
    }
    // x(0) -> B
    {
        const float* xin = g_emb + (size_t)nb * DD;
        for (int j = 0; j < 6; j++) {
            int idx = tid + 256 * j;
            if (idx < mcnt * DD) {
                int n = idx >> 6, k = idx & 63;
                *(__half*)(smem + SM_BH + n * SBROW + 2 * k) = __float2half_rn(xin[idx]);
            }
        }
    }
    __syncthreads();

    float cst[4][3][2];
    #pragma unroll
    for (int mt = 0; mt < 4; mt++)
        #pragma unroll
        for (int nt = 0; nt < 3; nt++) { cst[mt][nt][0] = 0.0f; cst[mt][nt][1] = 0.0f; }

    const uint4* gWlo = (const uint4*)g_WloF;
    const char* smw = smem + w * (NKT * 4 * 32 * 16);   // this warp's W_hi slice

    for (int t = 0; t < TT; t++) {
        // prefetch x(t+1) (global, latency hidden under mma phase)
        float xv[6];
        if (t + 1 < TT) {
            const float* xin = g_emb + ((size_t)(t + 1) * NN + nb) * DD;
            #pragma unroll
            for (int j = 0; j < 6; j++) {
                int idx = tid + 256 * j;
                xv[j] = (idx < mcnt * DD) ? __ldg(&xin[idx]) : 0.0f;
            }
        }

        // ---- mma mainloop (2 terms: Whi.B + Wlo.B)
        float acc[4][3][4];
        #pragma unroll
        for (int mt = 0; mt < 4; mt++)
            #pragma unroll
            for (int nt = 0; nt < 3; nt++)
                #pragma unroll
                for (int r = 0; r < 4; r++) acc[mt][nt][r] = 0.0f;

        #pragma unroll 2
        for (int kt = 0; kt < NKT; kt++) {
            uint32_t bh0[3], bh1[3];
            #pragma unroll
            for (int nt = 0; nt < 3; nt++) {
                int boffs = (nt * 8 + gid) * SBROW + (kt * 16 + tig * 2) * 2;
                bh0[nt] = *(const uint32_t*)(smem + SM_BH + boffs);
                bh1[nt] = *(const uint32_t*)(smem + SM_BH + boffs + 16);
            }
            #pragma unroll
            for (int mt = 0; mt < 4; mt++) {
                uint4 ah = *(const uint4*)(smw + ((kt * 4 + mt) * 32 + lane) * 16);
                uint4 al = __ldg(&gWlo[((w * NKT + kt) * 4 + mt) * 32 + lane]);
                #pragma unroll
                for (int nt = 0; nt < 3; nt++) {
                    mma_f16(acc[mt][nt], ah.x, ah.y, ah.z, ah.w, bh0[nt], bh1[nt]);
                    mma_f16(acc[mt][nt], al.x, al.y, al.z, al.w, bh0[nt], bh1[nt]);
                }
            }
        }
        __syncthreads();   // all B reads complete before anyone rewrites B

        // ---- epilogue: low threads (gid<4) hold (i,g); high threads (f,o) + state
        #pragma unroll
        for (int mt = 0; mt < 4; mt++) {
            #pragma unroll
            for (int nt = 0; nt < 3; nt++) {
                float vA0 = acc[mt][nt][0] + biasA[mt];
                float vA1 = acc[mt][nt][1] + biasA[mt];
                float vB0 = acc[mt][nt][2] + biasB[mt];
                float vB1 = acc[mt][nt][3] + biasB[mt];
                // low-half interpretation: p = sig(i)*tanh(g)
                float p0 = sigf(vA0) * tanhf_fast(vB0);
                float p1 = sigf(vA1) * tanhf_fast(vB1);
                float q0 = __shfl_xor_sync(0xffffffffu, p0, 16);
                float q1 = __shfl_xor_sync(0xffffffffu, p1, 16);
                if (gA) {   // high half: f,o + state update
                    float f0 = sigf(vA0), f1 = sigf(vA1);
                    float o0 = sigf(vB0), o1 = sigf(vB1);
                    float c0 = fmaf(f0, cst[mt][nt][0], q0);
                    float c1 = fmaf(f1, cst[mt][nt][1], q1);
                    cst[mt][nt][0] = c0; cst[mt][nt][1] = c1;
                    float h0 = o0 * tanhf_fast(c0);
                    float h1 = o1 * tanhf_fast(c1);
                    int unit = 16 * w + 4 * mt + q;
                    int n0 = nt * 8 + tig * 2, n1 = n0 + 1;
                    if (n0 < mcnt) {
                        *(__half*)(smem + SM_BH + n0 * SBROW + (DD + unit) * 2) = __float2half_rn(h0);
                        if (t == TT - 1) g_hfinal[(size_t)(nb + n0) * HH + unit] = h0;
                    }
                    if (n1 < mcnt) {
                        *(__half*)(smem + SM_BH + n1 * SBROW + (DD + unit) * 2) = __float2half_rn(h1);
                        if (t == TT - 1) g_hfinal[(size_t)(nb + n1) * HH + unit] = h1;
                    }
                }
            }
        }
        // store x(t+1)
        if (t + 1 < TT) {
            #pragma unroll
            for (int j = 0; j < 6; j++) {
                int idx = tid + 256 * j;
                if (idx < mcnt * DD) {
                    int n = idx >> 6, k = idx & 63;
                    *(__half*)(smem + SM_BH + n * SBROW + 2 * k) = __float2half_rn(xv[j]);
                }
            }
        }
        __syncthreads();   // B writes visible before next mainloop
    }
}

// ---------------- head MLP ----------------
__global__ void k_head(const float* __restrict__ Wm1, const float* __restrict__ bm1,
                       const float* __restrict__ Wm2, const float* __restrict__ bm2,
                       float* __restrict__ out) {
    __shared__ float hrow[HH];
    __shared__ float zred[2];
    int n = blockIdx.x, d = threadIdx.x;
    for (int i = d; i < HH; i += 64) hrow[i] = g_hfinal[(size_t)n * HH + i];
    __syncthreads();
    float acc = bm1[d];
    #pragma unroll 8
    for (int k = 0; k < HH; k++) acc = fmaf(hrow[k], Wm1[k * 64 + d], acc);
    acc = fmaxf(acc, 0.0f) * Wm2[d];
    #pragma unroll
    for (int o = 16; o; o >>= 1) acc += __shfl_down_sync(0xffffffffu, acc, o);
    if ((d & 31) == 0) zred[d >> 5] = acc;
    __syncthreads();
    if (d == 0) out[n] = zred[0] + zred[1] + bm2[0];
}

// ---------------- launch ----------------
extern "C" void kernel_launch(void* const* d_in, const int* in_sizes, int n_in,
                              void* d_out, int out_size) {
    (void)in_sizes; (void)n_in; (void)out_size;
    const float* x    = (const float*)d_in[0];
    const int*   ei   = (const int*)  d_in[1];
    const float* ew   = (const float*)d_in[2];
    const float* W1   = (const float*)d_in[3];
    const float* b1   = (const float*)d_in[4];
    const float* W2   = (const float*)d_in[5];
    const float* b2   = (const float*)d_in[6];
    const float* cb   = (const float*)d_in[7];
    const float* Wih  = (const float*)d_in[8];
    const float* Whh  = (const float*)d_in[9];
    const float* bih  = (const float*)d_in[10];
    const float* bhh  = (const float*)d_in[11];
    const float* Wm1  = (const float*)d_in[12];
    const float* bm1  = (const float*)d_in[13];
    const float* Wm2  = (const float*)d_in[14];
    const float* bm2  = (const float*)d_in[15];
    float* out = (float*)d_out;

    cudaFuncSetAttribute(k_lstm_mma, cudaFuncAttributeMaxDynamicSharedMemorySize, SM_TOTAL);

    k_init<<<(NN + 255) / 256, 256>>>();
    k_deg <<<(EE + 255) / 256, 256>>>(ei, ew);
    k_dinv<<<(NN + 255) / 256, 256>>>();
    k_scan<<<1, 1024>>>();
    k_fill<<<(EE + 255) / 256, 256>>>(ei, ew);
    k_prepw<<<NFRAG / 256, 256>>>(Wih, Whh);

    k_gcn1<<<4096, 256>>>(x, W1);
    dim3 aggGrid(NN, TT / 2);
    k_agg<<<aggGrid, 64>>>(1, b1, nullptr);
    k_gcn2<<<4096, 256>>>(W2);
    k_agg<<<aggGrid, 64>>>(2, b2, cb);

    k_lstm_mma<<<NBLK, 256, SM_TOTAL>>>(bih, bhh);
    k_head<<<NN, 64>>>(Wm1, bm1, Wm2, bm2, out);
}

// round 15
// speedup vs baseline: 3.6804x; 1.2536x over previous
#include <cuda_runtime.h>
#include <cuda_fp16.h>
#include <cstddef>
#include <cstdint>

// ---------------- problem constants ----------------
#define TT   336
#define NN   3233
#define EE   20000
#define FEAT 14
#define DD   64
#define HH   128
#define G4   512
#define KTOT 192
#define MNODES 22
#define NBLK 147
#define NTP  24            // padded node tile (3 n-tiles of 8)
#define NKT  12            // k-tiles of 16
#define SBROW 400          // B row stride bytes (bank-spread)

// fragment-ordered W: [w][kt][mt][lane][reg] -> 8*12*4*32*4 = 49152 uint32
#define NFRAG 49152
#define WSM_BYTES (NFRAG * 4)          // 196608 B of W in SMEM
#define SM_BH  WSM_BYTES               // B: 24 x 400 (single fp16 operand)
#define SM_TOTAL (SM_BH + NTP * SBROW)   // 206208 B

// ---------------- device scratch ----------------
__device__ float g_deg[NN];
__device__ float g_dinv[NN];
__device__ int   g_cnt[NN];
__device__ int   g_fill[NN];
__device__ int   g_rowptr[NN + 1];
__device__ int   g_srcs[EE];
__device__ float g_norms[EE];

__device__ float g_hw1[(size_t)TT * NN * DD];
__device__ float g_h1 [(size_t)TT * NN * DD];
__device__ float g_hw2[(size_t)TT * NN * DD];
__device__ float g_emb[(size_t)TT * NN * DD];
__device__ float g_hfinal[NN * HH];

__device__ uint32_t g_WhiF[NFRAG];   // f16x2 W fragments

// ---------------- activations ----------------
__device__ __forceinline__ float sigf(float x) {
    return __fdividef(1.0f, 1.0f + __expf(-x));
}
__device__ __forceinline__ float tanhf_fast(float x) {
    return 2.0f * sigf(2.0f * x) - 1.0f;
}

// ---------------- warp mma (fp16 -> fp32), sm_80+ path ----------------
__device__ __forceinline__ void mma_f16(float* c, uint32_t a0, uint32_t a1,
                                        uint32_t a2, uint32_t a3,
                                        uint32_t b0, uint32_t b1) {
    asm volatile("mma.sync.aligned.m16n8k16.row.col.f32.f16.f16.f32 "
                 "{%0,%1,%2,%3},{%4,%5,%6,%7},{%8,%9},{%0,%1,%2,%3};"
                 : "+f"(c[0]), "+f"(c[1]), "+f"(c[2]), "+f"(c[3])
                 : "r"(a0), "r"(a1), "r"(a2), "r"(a3), "r"(b0), "r"(b1));
}

// ---------------- graph prep (known-good) ----------------
__global__ void k_init() {
    int n = blockIdx.x * blockDim.x + threadIdx.x;
    if (n < NN) { g_deg[n] = 1.0f; g_cnt[n] = 0; g_fill[n] = 0; }
}
__global__ void k_deg(const int* __restrict__ ei, const float* __restrict__ ew) {
    int e = blockIdx.x * blockDim.x + threadIdx.x;
    if (e < EE) {
        int dn = ei[EE + e];
        atomicAdd(&g_deg[dn], ew[e]);
        atomicAdd(&g_cnt[dn], 1);
    }
}
__global__ void k_dinv() {
    int n = blockIdx.x * blockDim.x + threadIdx.x;
    if (n < NN) g_dinv[n] = rsqrtf(g_deg[n]);
}
__global__ void k_scan() {
    __shared__ int warpsum[32];
    int tid = threadIdx.x;
    int base = tid * 4;
    int v[4]; int s = 0;
    #pragma unroll
    for (int i = 0; i < 4; i++) {
        int c = (base + i < NN) ? g_cnt[base + i] : 0;
        v[i] = s; s += c;
    }
    int lane = tid & 31, wid = tid >> 5;
    int inc = s;
    #pragma unroll
    for (int o = 1; o < 32; o <<= 1) {
        int t2 = __shfl_up_sync(0xffffffffu, inc, o);
        if (lane >= o) inc += t2;
    }
    if (lane == 31) warpsum[wid] = inc;
    __syncthreads();
    if (wid == 0) {
        int ws = warpsum[lane];
        #pragma unroll
        for (int o = 1; o < 32; o <<= 1) {
            int t2 = __shfl_up_sync(0xffffffffu, ws, o);
            if (lane >= o) ws += t2;
        }
        warpsum[lane] = ws;
    }
    __syncthreads();
    int excl = inc - s + (wid ? warpsum[wid - 1] : 0);
    #pragma unroll
    for (int i = 0; i < 4; i++)
        if (base + i < NN) g_rowptr[base + i] = excl + v[i];
    if (tid == 1023) g_rowptr[NN] = excl + s;
}
__global__ void k_fill(const int* __restrict__ ei, const float* __restrict__ ew) {
    int e = blockIdx.x * blockDim.x + threadIdx.x;
    if (e < EE) {
        int sn = ei[e], dn = ei[EE + e];
        int pos = g_rowptr[dn] + atomicAdd(&g_fill[dn], 1);
        g_srcs[pos]  = sn;
        g_norms[pos] = g_dinv[sn] * ew[e] * g_dinv[dn];
    }
}

// ---------------- W fragment prep (single fp16) ----------------
// Gate-row permutation: warp w, m-tile mt, local row r (0..15):
//   gate = r/4 (i,f,g,o), unit = 16w + 4mt + r%4, orig row = gate*128 + unit.
// Fragment idx layout: (((w*12 + kt)*4 + mt)*32 + lane)*4 + reg, each reg = f16x2 (k, k+1).
__global__ void k_prepw(const float* __restrict__ Wih, const float* __restrict__ Whh) {
    int idx = blockIdx.x * blockDim.x + threadIdx.x;
    if (idx >= NFRAG) return;
    int reg  = idx & 3;
    int lane = (idx >> 2) & 31;
    int mt   = (idx >> 7) & 3;
    int kt   = (idx >> 9) % 12;
    int w    = idx / 6144;
    int gid = lane >> 2, tig = lane & 3;
    int r = ((reg == 0 || reg == 2) ? gid : gid + 8);
    int k = 16 * kt + tig * 2 + ((reg >= 2) ? 8 : 0);
    int row = (r >> 2) * 128 + 16 * w + 4 * mt + (r & 3);
    float v0 = (k     < DD) ? Wih[row * DD + k]       : Whh[row * HH + (k - DD)];
    float v1 = (k + 1 < DD) ? Wih[row * DD + k + 1]   : Whh[row * HH + (k + 1 - DD)];
    __half h0 = __float2half_rn(v0), h1 = __float2half_rn(v1);
    g_WhiF[idx] = (uint32_t)__half_as_ushort(h0) | ((uint32_t)__half_as_ushort(h1) << 16);
}

// ---------------- GCN stages (exact 9085us-baseline code) ----------------
__global__ __launch_bounds__(256) void k_gcn1(const float* __restrict__ x,
                                              const float* __restrict__ W1) {
    int d = threadIdx.x & 63;
    float wcol[FEAT];
    #pragma unroll
    for (int f = 0; f < FEAT; f++) wcol[f] = W1[f * DD + d];
    __shared__ float xs[4][FEAT];
    size_t totalRows = (size_t)TT * NN;
    for (size_t r0 = (size_t)blockIdx.x * 4; r0 < totalRows; r0 += (size_t)gridDim.x * 4) {
        __syncthreads();
        if (threadIdx.x < 4 * FEAT)
            ((float*)xs)[threadIdx.x] = x[r0 * FEAT + threadIdx.x];
        __syncthreads();
        int rr = threadIdx.x >> 6;
        float acc = 0.0f;
        #pragma unroll
        for (int f = 0; f < FEAT; f++) acc = fmaf(xs[rr][f], wcol[f], acc);
        g_hw1[r0 * DD + threadIdx.x] = acc;
    }
}
__global__ __launch_bounds__(256) void k_gcn2(const float* __restrict__ W2) {
    int d = threadIdx.x & 63;
    float wcol[DD];
    #pragma unroll
    for (int f = 0; f < DD; f++) wcol[f] = W2[f * DD + d];
    __shared__ __align__(16) float rows[4][DD];
    size_t totalRows = (size_t)TT * NN;
    for (size_t r0 = (size_t)blockIdx.x * 4; r0 < totalRows; r0 += (size_t)gridDim.x * 4) {
        __syncthreads();
        ((float*)rows)[threadIdx.x] = g_h1[r0 * DD + threadIdx.x];
        __syncthreads();
        int rr = threadIdx.x >> 6;
        float acc = 0.0f;
        #pragma unroll
        for (int f = 0; f < DD; f += 4) {
            float4 a = *(const float4*)&rows[rr][f];
            acc = fmaf(a.x, wcol[f],     acc);
            acc = fmaf(a.y, wcol[f + 1], acc);
            acc = fmaf(a.z, wcol[f + 2], acc);
            acc = fmaf(a.w, wcol[f + 3], acc);
        }
        g_hw2[r0 * DD + threadIdx.x] = acc;
    }
}
__global__ void k_agg(int layer, const float* __restrict__ b, const float* __restrict__ cb) {
    int n = blockIdx.x, t0 = blockIdx.y * 2, d = threadIdx.x;
    const float* hw = (layer == 1) ? g_hw1 : g_hw2;
    const float* hwt0 = hw + (size_t)t0 * NN * DD;
    const float* hwt1 = hwt0 + (size_t)NN * DD;
    float di = g_dinv[n];
    float sw = di * di;
    float acc0 = sw * __ldg(&hwt0[(size_t)n * DD + d]);
    float acc1 = sw * __ldg(&hwt1[(size_t)n * DD + d]);
    int s = g_rowptr[n], e = g_rowptr[n + 1];
    for (int i = s; i < e; i++) {
        int    sn = g_srcs[i];
        float  w  = g_norms[i];
        size_t o  = (size_t)sn * DD + d;
        acc0 = fmaf(w, __ldg(&hwt0[o]), acc0);
        acc1 = fmaf(w, __ldg(&hwt1[o]), acc1);
    }
    float bv = b[d];
    acc0 += bv; acc1 += bv;
    float* o;
    if (layer == 1) {
        acc0 = fmaxf(acc0, 0.0f); acc1 = fmaxf(acc1, 0.0f); o = g_h1;
    } else {
        float cbv = cb[(size_t)n * DD + d];
        acc0 += cbv; acc1 += cbv; o = g_emb;
    }
    o[((size_t)t0 * NN + n) * DD + d] = acc0;
    o[((size_t)(t0 + 1) * NN + n) * DD + d] = acc1;
}

// ---------------- persistent LSTM on mma.sync fp16 (single-term) ----------------
// gates[512 x 24] = W[512 x 192] . B[24 x 192]^T per step; W and B both fp16
// (repr err ~2^-11 each -> final ~2-3e-4, within 1e-3 budget).
// W fragments resident in SMEM (LDS.128). Warp w owns units 16w..16w+15:
// each m-tile = 4 units x gates {i,f,g,o} -> epilogue pairs (i,g)/(f,o) via shfl_xor(16).
__global__ __launch_bounds__(256, 1) void k_lstm_mma(const float* __restrict__ bih,
                                                     const float* __restrict__ bhh) {
    extern __shared__ char smem[];
    int tid = threadIdx.x;
    int w = tid >> 5, lane = tid & 31;
    int gid = lane >> 2, tig = lane & 3, q = gid & 3;
    int nb = blockIdx.x * MNODES;
    int mcnt = min(MNODES, NN - nb);

    // ---- init: W -> SMEM, zero B region
    {
        const uint4* src = (const uint4*)g_WhiF;
        uint4* dst = (uint4*)smem;
        for (int i = tid; i < WSM_BYTES / 16; i += 256) dst[i] = __ldg(&src[i]);
        uint32_t* bz = (uint32_t*)(smem + SM_BH);
        for (int i = tid; i < (NTP * SBROW) / 4; i += 256) bz[i] = 0u;
    }
    // biases for this thread's gate rows: biasA = gate (i|f), biasB = gate (g|o)
    int gA = gid >> 2;                    // 0: low half (i,g); 1: high half (f,o)
    float biasA[4], biasB[4];
    #pragma unroll
    for (int mt = 0; mt < 4; mt++) {
        int unit = 16 * w + 4 * mt + q;
        biasA[mt] = bih[gA * 128 + unit] + bhh[gA * 128 + unit];
        biasB[mt] = bih[(gA + 2) * 128 + unit] + bhh[(gA + 2) * 128 + unit];
    }
    // x(0) -> B
    {
        const float* xin = g_emb + (size_t)nb * DD;
        for (int j = 0; j < 6; j++) {
            int idx = tid + 256 * j;
            if (idx < mcnt * DD) {
                int n = idx >> 6, k = idx & 63;
                *(__half*)(smem + SM_BH + n * SBROW + 2 * k) = __float2half_rn(xin[idx]);
            }
        }
    }
    __syncthreads();

    float cst[4][3][2];
    #pragma unroll
    for (int mt = 0; mt < 4; mt++)
        #pragma unroll
        for (int nt = 0; nt < 3; nt++) { cst[mt][nt][0] = 0.0f; cst[mt][nt][1] = 0.0f; }

    const char* smw = smem + w * (NKT * 4 * 32 * 16);   // this warp's W slice

    for (int t = 0; t < TT; t++) {
        // prefetch x(t+1) (global, latency hidden under mma phase)
        float xv[6];
        if (t + 1 < TT) {
            const float* xin = g_emb + ((size_t)(t + 1) * NN + nb) * DD;
            #pragma unroll
            for (int j = 0; j < 6; j++) {
                int idx = tid + 256 * j;
                xv[j] = (idx < mcnt * DD) ? __ldg(&xin[idx]) : 0.0f;
            }
        }

        // ---- mma mainloop (single term: W.B)
        float acc[4][3][4];
        #pragma unroll
        for (int mt = 0; mt < 4; mt++)
            #pragma unroll
            for (int nt = 0; nt < 3; nt++)
                #pragma unroll
                for (int r = 0; r < 4; r++) acc[mt][nt][r] = 0.0f;

        #pragma unroll 2
        for (int kt = 0; kt < NKT; kt++) {
            uint32_t bh0[3], bh1[3];
            #pragma unroll
            for (int nt = 0; nt < 3; nt++) {
                int boffs = (nt * 8 + gid) * SBROW + (kt * 16 + tig * 2) * 2;
                bh0[nt] = *(const uint32_t*)(smem + SM_BH + boffs);
                bh1[nt] = *(const uint32_t*)(smem + SM_BH + boffs + 16);
            }
            #pragma unroll
            for (int mt = 0; mt < 4; mt++) {
                uint4 ah = *(const uint4*)(smw + ((kt * 4 + mt) * 32 + lane) * 16);
                #pragma unroll
                for (int nt = 0; nt < 3; nt++)
                    mma_f16(acc[mt][nt], ah.x, ah.y, ah.z, ah.w, bh0[nt], bh1[nt]);
            }
        }
        __syncthreads();   // all B reads complete before anyone rewrites B

        // ---- epilogue: low threads (gid<4) hold (i,g); high threads (f,o) + state
        #pragma unroll
        for (int mt = 0; mt < 4; mt++) {
            #pragma unroll
            for (int nt = 0; nt < 3; nt++) {
                float vA0 = acc[mt][nt][0] + biasA[mt];
                float vA1 = acc[mt][nt][1] + biasA[mt];
                float vB0 = acc[mt][nt][2] + biasB[mt];
                float vB1 = acc[mt][nt][3] + biasB[mt];
                // low-half interpretation: p = sig(i)*tanh(g)
                float p0 = sigf(vA0) * tanhf_fast(vB0);
                float p1 = sigf(vA1) * tanhf_fast(vB1);
                float q0 = __shfl_xor_sync(0xffffffffu, p0, 16);
                float q1 = __shfl_xor_sync(0xffffffffu, p1, 16);
                if (gA) {   // high half: f,o + state update
                    float f0 = sigf(vA0), f1 = sigf(vA1);
                    float o0 = sigf(vB0), o1 = sigf(vB1);
                    float c0 = fmaf(f0, cst[mt][nt][0], q0);
                    float c1 = fmaf(f1, cst[mt][nt][1], q1);
                    cst[mt][nt][0] = c0; cst[mt][nt][1] = c1;
                    float h0 = o0 * tanhf_fast(c0);
                    float h1 = o1 * tanhf_fast(c1);
                    int unit = 16 * w + 4 * mt + q;
                    int n0 = nt * 8 + tig * 2, n1 = n0 + 1;
                    if (n0 < mcnt) {
                        *(__half*)(smem + SM_BH + n0 * SBROW + (DD + unit) * 2) = __float2half_rn(h0);
                        if (t == TT - 1) g_hfinal[(size_t)(nb + n0) * HH + unit] = h0;
                    }
                    if (n1 < mcnt) {
                        *(__half*)(smem + SM_BH + n1 * SBROW + (DD + unit) * 2) = __float2half_rn(h1);
                        if (t == TT - 1) g_hfinal[(size_t)(nb + n1) * HH + unit] = h1;
                    }
                }
            }
        }
        // store x(t+1)
        if (t + 1 < TT) {
            #pragma unroll
            for (int j = 0; j < 6; j++) {
                int idx = tid + 256 * j;
                if (idx < mcnt * DD) {
                    int n = idx >> 6, k = idx & 63;
                    *(__half*)(smem + SM_BH + n * SBROW + 2 * k) = __float2half_rn(xv[j]);
                }
            }
        }
        __syncthreads();   // B writes visible before next mainloop
    }
}

// ---------------- head MLP ----------------
__global__ void k_head(const float* __restrict__ Wm1, const float* __restrict__ bm1,
                       const float* __restrict__ Wm2, const float* __restrict__ bm2,
                       float* __restrict__ out) {
    __shared__ float hrow[HH];
    __shared__ float zred[2];
    int n = blockIdx.x, d = threadIdx.x;
    for (int i = d; i < HH; i += 64) hrow[i] = g_hfinal[(size_t)n * HH + i];
    __syncthreads();
    float acc = bm1[d];
    #pragma unroll 8
    for (int k = 0; k < HH; k++) acc = fmaf(hrow[k], Wm1[k * 64 + d], acc);
    acc = fmaxf(acc, 0.0f) * Wm2[d];
    #pragma unroll
    for (int o = 16; o; o >>= 1) acc += __shfl_down_sync(0xffffffffu, acc, o);
    if ((d & 31) == 0) zred[d >> 5] = acc;
    __syncthreads();
    if (d == 0) out[n] = zred[0] + zred[1] + bm2[0];
}

// ---------------- launch ----------------
extern "C" void kernel_launch(void* const* d_in, const int* in_sizes, int n_in,
                              void* d_out, int out_size) {
    (void)in_sizes; (void)n_in; (void)out_size;
    const float* x    = (const float*)d_in[0];
    const int*   ei   = (const int*)  d_in[1];
    const float* ew   = (const float*)d_in[2];
    const float* W1   = (const float*)d_in[3];
    const float* b1   = (const float*)d_in[4];
    const float* W2   = (const float*)d_in[5];
    const float* b2   = (const float*)d_in[6];
    const float* cb   = (const float*)d_in[7];
    const float* Wih  = (const float*)d_in[8];
    const float* Whh  = (const float*)d_in[9];
    const float* bih  = (const float*)d_in[10];
    const float* bhh  = (const float*)d_in[11];
    const float* Wm1  = (const float*)d_in[12];
    const float* bm1  = (const float*)d_in[13];
    const float* Wm2  = (const float*)d_in[14];
    const float* bm2  = (const float*)d_in[15];
    float* out = (float*)d_out;

    cudaFuncSetAttribute(k_lstm_mma, cudaFuncAttributeMaxDynamicSharedMemorySize, SM_TOTAL);

    k_init<<<(NN + 255) / 256, 256>>>();
    k_deg <<<(EE + 255) / 256, 256>>>(ei, ew);
    k_dinv<<<(NN + 255) / 256, 256>>>();
    k_scan<<<1, 1024>>>();
    k_fill<<<(EE + 255) / 256, 256>>>(ei, ew);
    k_prepw<<<NFRAG / 256, 256>>>(Wih, Whh);

    k_gcn1<<<4096, 256>>>(x, W1);
    dim3 aggGrid(NN, TT / 2);
    k_agg<<<aggGrid, 64>>>(1, b1, nullptr);
    k_gcn2<<<4096, 256>>>(W2);
    k_agg<<<aggGrid, 64>>>(2, b2, cb);

    k_lstm_mma<<<NBLK, 256, SM_TOTAL>>>(bih, bhh);
    k_head<<<NN, 64>>>(Wm1, bm1, Wm2, bm2, out);
}